// round 2
// baseline (speedup 1.0000x reference)
#include <cuda_runtime.h>

#define BATCH 32
#define CCH 256
#define HHH 56
#define WWW 56
#define HWSZ (HHH*WWW)          // 3136
#define CHWSZ (CCH*HWSZ)        // 802816
#define NPIX (BATCH*HWSZ)       // 100352
#define K3 (CCH*9)              // 2304
#define K1 CCH                  // 256
#define EPSF 1e-5f

#define COTILE 128
#define PIXTILE 128
#define KCHUNK 16
#define NT 256
#define APAD 4                  // float2 pad to break smem store conflicts

// ---------------- device scratch (no allocations allowed) ----------------
__device__ float g_r[(size_t)BATCH * CHWSZ];     // intermediate activation (~103 MB)
__device__ float g_qw1[CCH * K3];
__device__ float g_qw2[CCH * K3];
__device__ float g_qws[CCH * K1];
__device__ unsigned g_maxbits[4];

// packed dual-fp32 FMA (sm_100+ PTX; 2x FFMA throughput, bitwise == scalar FFMA)
__device__ __forceinline__ void ffma2(unsigned long long& d,
                                      unsigned long long a,
                                      unsigned long long b) {
    asm("fma.rn.f32x2 %0, %1, %2, %0;" : "+l"(d) : "l"(a), "l"(b));
}

// ---------------- weight fake-quant ----------------
__global__ void zero_max_kernel() {
    if (threadIdx.x < 4) g_maxbits[threadIdx.x] = 0u;
}

__global__ void absmax_kernel(const float* __restrict__ w, int n, int slot) {
    __shared__ unsigned sm[NT];
    unsigned m = 0u;
    for (int i = blockIdx.x * blockDim.x + threadIdx.x; i < n; i += gridDim.x * blockDim.x) {
        unsigned b = __float_as_uint(fabsf(w[i]));  // nonneg floats: uint order == float order
        m = max(m, b);
    }
    sm[threadIdx.x] = m;
    __syncthreads();
    for (int s = NT / 2; s > 0; s >>= 1) {
        if (threadIdx.x < s) sm[threadIdx.x] = max(sm[threadIdx.x], sm[threadIdx.x + s]);
        __syncthreads();
    }
    if (threadIdx.x == 0) atomicMax(&g_maxbits[slot], sm[0]);
}

__global__ void quantw_kernel(const float* __restrict__ w, float* __restrict__ qw,
                              int n, int slot) {
    float s = __uint_as_float(g_maxbits[slot]) / 7.0f;
    for (int i = blockIdx.x * blockDim.x + threadIdx.x; i < n; i += gridDim.x * blockDim.x) {
        float v = w[i] / s;                               // true division: match reference rounding
        v = fminf(fmaxf(v, -7.0f), 7.0f);
        qw[i] = rintf(v) * s;                             // rintf == round-half-even == jnp.round
    }
}

// ---------------- fused conv (+optional 1x1 shortcut) + BN + uint4 fake-quant ----------------
// out[co, pix] = act_sbn( conv3x3(src3, qw3) [+ conv1x1(src1, qw1x1)] )
__global__ __launch_bounds__(NT, 2)
void conv_kernel(const float* __restrict__ src3,
                 const float* __restrict__ qw3,
                 const float* __restrict__ src1,    // nullptr -> no shortcut phase
                 const float* __restrict__ qw1x1,
                 const float* __restrict__ gamma, const float* __restrict__ beta,
                 const float* __restrict__ mean,  const float* __restrict__ var,
                 const float* __restrict__ step,
                 float* __restrict__ out) {
    __shared__ __align__(16) float2 sA[KCHUNK][COTILE + APAD]; // weights duplicated {w,w}
    __shared__ __align__(16) float  sB[KCHUNK][PIXTILE];       // activations
    __shared__ int sPbase[PIXTILE];
    __shared__ int sPy[PIXTILE];
    __shared__ int sPx[PIXTILE];

    const int tid = threadIdx.x;
    const int pixBase = blockIdx.x * PIXTILE;
    const int coBase  = blockIdx.y * COTILE;

    if (tid < PIXTILE) {
        int p = pixBase + tid;
        int b = p / HWSZ;
        int rem = p - b * HWSZ;
        int y = rem / WWW;
        int x = rem - y * WWW;
        sPbase[tid] = b * CHWSZ + y * WWW + x;
        sPy[tid] = y;
        sPx[tid] = x;
    }
    __syncthreads();

    const int ty = tid >> 4;   // 0..15 -> 8 output channels each
    const int tx = tid & 15;   // 0..15 -> 8 pixels each (4 f32x2 pairs)

    unsigned long long acc[32];
#pragma unroll
    for (int i = 0; i < 32; i++) acc[i] = 0ull;

    // ---- phase 1: 3x3 conv over src3 ----
    for (int k0 = 0; k0 < K3; k0 += KCHUNK) {
#pragma unroll
        for (int r = 0; r < (KCHUNK * COTILE) / NT; r++) {     // weights
            int idx = r * NT + tid;
            int kk = idx & (KCHUNK - 1);
            int co = idx >> 4;
            float wv = qw3[(coBase + co) * K3 + k0 + kk];
            sA[kk][co] = make_float2(wv, wv);
        }
#pragma unroll
        for (int r = 0; r < (KCHUNK * PIXTILE) / NT; r++) {    // activations (zero-padded halo)
            int idx = r * NT + tid;
            int i  = idx & (PIXTILE - 1);
            int kk = idx >> 7;
            int k  = k0 + kk;
            int ci = k / 9;
            int r9 = k - ci * 9;
            int dy = r9 / 3 - 1;
            int dx = r9 - (r9 / 3) * 3 - 1;
            int y2 = sPy[i] + dy;
            int x2 = sPx[i] + dx;
            float v = 0.0f;
            if ((unsigned)y2 < (unsigned)HHH && (unsigned)x2 < (unsigned)WWW)
                v = __ldg(&src3[sPbase[i] + ci * HWSZ + dy * WWW + dx]);
            sB[kk][i] = v;
        }
        __syncthreads();
#pragma unroll
        for (int kk = 0; kk < KCHUNK; kk++) {
            const ulonglong2* Ap = reinterpret_cast<const ulonglong2*>(&sA[kk][ty * 8]);
            const ulonglong2* Bp = reinterpret_cast<const ulonglong2*>(&sB[kk][tx * 8]);
            ulonglong2 bv0 = Bp[0];
            ulonglong2 bv1 = Bp[1];
#pragma unroll
            for (int c2 = 0; c2 < 4; c2++) {
                ulonglong2 av = Ap[c2];
                ffma2(acc[c2 * 8 + 0], av.x, bv0.x);
                ffma2(acc[c2 * 8 + 1], av.x, bv0.y);
                ffma2(acc[c2 * 8 + 2], av.x, bv1.x);
                ffma2(acc[c2 * 8 + 3], av.x, bv1.y);
                ffma2(acc[c2 * 8 + 4], av.y, bv0.x);
                ffma2(acc[c2 * 8 + 5], av.y, bv0.y);
                ffma2(acc[c2 * 8 + 6], av.y, bv1.x);
                ffma2(acc[c2 * 8 + 7], av.y, bv1.y);
            }
        }
        __syncthreads();
    }

    // ---- phase 2: optional 1x1 shortcut conv over src1 ----
    if (src1 != nullptr) {
        for (int k0 = 0; k0 < K1; k0 += KCHUNK) {
#pragma unroll
            for (int r = 0; r < (KCHUNK * COTILE) / NT; r++) {
                int idx = r * NT + tid;
                int kk = idx & (KCHUNK - 1);
                int co = idx >> 4;
                float wv = qw1x1[(coBase + co) * K1 + k0 + kk];
                sA[kk][co] = make_float2(wv, wv);
            }
#pragma unroll
            for (int r = 0; r < (KCHUNK * PIXTILE) / NT; r++) {
                int idx = r * NT + tid;
                int i  = idx & (PIXTILE - 1);
                int kk = idx >> 7;
                sB[kk][i] = __ldg(&src1[sPbase[i] + (k0 + kk) * HWSZ]);
            }
            __syncthreads();
#pragma unroll
            for (int kk = 0; kk < KCHUNK; kk++) {
                const ulonglong2* Ap = reinterpret_cast<const ulonglong2*>(&sA[kk][ty * 8]);
                const ulonglong2* Bp = reinterpret_cast<const ulonglong2*>(&sB[kk][tx * 8]);
                ulonglong2 bv0 = Bp[0];
                ulonglong2 bv1 = Bp[1];
#pragma unroll
                for (int c2 = 0; c2 < 4; c2++) {
                    ulonglong2 av = Ap[c2];
                    ffma2(acc[c2 * 8 + 0], av.x, bv0.x);
                    ffma2(acc[c2 * 8 + 1], av.x, bv0.y);
                    ffma2(acc[c2 * 8 + 2], av.x, bv1.x);
                    ffma2(acc[c2 * 8 + 3], av.x, bv1.y);
                    ffma2(acc[c2 * 8 + 4], av.y, bv0.x);
                    ffma2(acc[c2 * 8 + 5], av.y, bv0.y);
                    ffma2(acc[c2 * 8 + 6], av.y, bv1.x);
                    ffma2(acc[c2 * 8 + 7], av.y, bv1.y);
                }
            }
            __syncthreads();
        }
    }

    // ---- epilogue: BN + uint4 fake-quant, float2 stores ----
#pragma unroll
    for (int cl = 0; cl < 8; cl++) {
        int c = coBase + ty * 8 + cl;
        float gm = gamma[c], bt = beta[c], mn = mean[c], vr = var[c], st = step[c];
        float rs = 1.0f / sqrtf(vr + EPSF);
#pragma unroll
        for (int j = 0; j < 4; j++) {
            unsigned long long a = acc[(cl >> 1) * 8 + (cl & 1) * 4 + j];
            float lo = __uint_as_float((unsigned)(a & 0xffffffffu));
            float hi = __uint_as_float((unsigned)(a >> 32));
            float ylo = gm * (lo - mn) * rs + bt;
            float yhi = gm * (hi - mn) * rs + bt;
            float qlo = fminf(fmaxf(rintf(ylo / st), 0.0f), 15.0f) * st;
            float qhi = fminf(fmaxf(rintf(yhi / st), 0.0f), 15.0f) * st;
            int i0 = tx * 8 + j * 2;  // even pixel: never crosses an image boundary
            float2* dst = reinterpret_cast<float2*>(&out[sPbase[i0] + c * HWSZ]);
            *dst = make_float2(qlo, qhi);
        }
    }
}

// ---------------- launch ----------------
extern "C" void kernel_launch(void* const* d_in, const int* in_sizes, int n_in,
                              void* d_out, int out_size) {
    const float* x  = (const float*)d_in[0];
    const float* w1 = (const float*)d_in[1];
    const float* w2 = (const float*)d_in[2];
    const float* ws = (const float*)d_in[3];
    const float* g1 = (const float*)d_in[4];
    const float* b1 = (const float*)d_in[5];
    const float* m1 = (const float*)d_in[6];
    const float* v1 = (const float*)d_in[7];
    const float* s1 = (const float*)d_in[8];
    const float* g2 = (const float*)d_in[9];
    const float* b2 = (const float*)d_in[10];
    const float* m2 = (const float*)d_in[11];
    const float* v2 = (const float*)d_in[12];
    const float* s2 = (const float*)d_in[13];
    float* out = (float*)d_out;

    void* p;
    cudaGetSymbolAddress(&p, g_r);   float* rbuf = (float*)p;
    cudaGetSymbolAddress(&p, g_qw1); float* qw1  = (float*)p;
    cudaGetSymbolAddress(&p, g_qw2); float* qw2  = (float*)p;
    cudaGetSymbolAddress(&p, g_qws); float* qws  = (float*)p;

    zero_max_kernel<<<1, 32>>>();
    absmax_kernel<<<148, NT>>>(w1, CCH * K3, 0);
    absmax_kernel<<<148, NT>>>(w2, CCH * K3, 1);
    absmax_kernel<<<64,  NT>>>(ws, CCH * K1, 2);
    quantw_kernel<<<256, NT>>>(w1, qw1, CCH * K3, 0);
    quantw_kernel<<<256, NT>>>(w2, qw2, CCH * K3, 1);
    quantw_kernel<<<64,  NT>>>(ws, qws, CCH * K1, 2);

    dim3 grid(NPIX / PIXTILE, CCH / COTILE);   // (784, 2)
    // conv1: 3x3 on x -> BN1 + uint4 quant -> rbuf
    conv_kernel<<<grid, NT>>>(x, qw1, nullptr, nullptr, g1, b1, m1, v1, s1, rbuf);
    // conv2: 3x3 on rbuf + fused 1x1 shortcut on x -> BN2 + uint4 quant -> out
    conv_kernel<<<grid, NT>>>(rbuf, qw2, x, qws, g2, b2, m2, v2, s2, out);
}

// round 3
// speedup vs baseline: 1.0005x; 1.0005x over previous
#include <cuda_runtime.h>

#define BATCH 32
#define CCH 256
#define HHH 56
#define WWW 56
#define HWSZ (HHH*WWW)          // 3136
#define CHWSZ (CCH*HWSZ)        // 802816
#define NPIX (BATCH*HWSZ)       // 100352
#define K3 (CCH*9)              // 2304
#define K1 CCH                  // 256
#define EPSF 1e-5f

#define COTILE 128
#define PIXTILE 128
#define KCHUNK 16
#define NT 256
#define APAD 4                  // float2 pad to break smem store conflicts

// ---------------- device scratch (no allocations allowed) ----------------
__device__ float g_r[(size_t)BATCH * CHWSZ];     // intermediate activation (~103 MB)
__device__ float g_qw1[CCH * K3];
__device__ float g_qw2[CCH * K3];
__device__ float g_qws[CCH * K1];
__device__ unsigned g_maxbits[4];

// packed dual-fp32 FMA (sm_100+ PTX; 2x FFMA throughput, bitwise == scalar FFMA)
__device__ __forceinline__ void ffma2(unsigned long long& d,
                                      unsigned long long a,
                                      unsigned long long b) {
    asm("fma.rn.f32x2 %0, %1, %2, %0;" : "+l"(d) : "l"(a), "l"(b));
}

// ---------------- weight fake-quant ----------------
__global__ void zero_max_kernel() {
    if (threadIdx.x < 4) g_maxbits[threadIdx.x] = 0u;
}

__global__ void absmax_kernel(const float* __restrict__ w, int n, int slot) {
    __shared__ unsigned sm[NT];
    unsigned m = 0u;
    for (int i = blockIdx.x * blockDim.x + threadIdx.x; i < n; i += gridDim.x * blockDim.x) {
        unsigned b = __float_as_uint(fabsf(w[i]));  // nonneg floats: uint order == float order
        m = max(m, b);
    }
    sm[threadIdx.x] = m;
    __syncthreads();
    for (int s = NT / 2; s > 0; s >>= 1) {
        if (threadIdx.x < s) sm[threadIdx.x] = max(sm[threadIdx.x], sm[threadIdx.x + s]);
        __syncthreads();
    }
    if (threadIdx.x == 0) atomicMax(&g_maxbits[slot], sm[0]);
}

__global__ void quantw_kernel(const float* __restrict__ w, float* __restrict__ qw,
                              int n, int slot) {
    float s = __uint_as_float(g_maxbits[slot]) / 7.0f;
    for (int i = blockIdx.x * blockDim.x + threadIdx.x; i < n; i += gridDim.x * blockDim.x) {
        float v = w[i] / s;                               // true division: match reference rounding
        v = fminf(fmaxf(v, -7.0f), 7.0f);
        qw[i] = rintf(v) * s;                             // rintf == round-half-even == jnp.round
    }
}

// ---------------- fused conv (+optional 1x1 shortcut) + BN + uint4 fake-quant ----------------
// out[co, pix] = act_sbn( conv3x3(src3, qw3) [+ conv1x1(src1, qw1x1)] )
__global__ __launch_bounds__(NT, 2)
void conv_kernel(const float* __restrict__ src3,
                 const float* __restrict__ qw3,
                 const float* __restrict__ src1,    // nullptr -> no shortcut phase
                 const float* __restrict__ qw1x1,
                 const float* __restrict__ gamma, const float* __restrict__ beta,
                 const float* __restrict__ mean,  const float* __restrict__ var,
                 const float* __restrict__ step,
                 float* __restrict__ out) {
    __shared__ __align__(16) float2 sA[KCHUNK][COTILE + APAD]; // weights duplicated {w,w}
    __shared__ __align__(16) float  sB[KCHUNK][PIXTILE];       // activations
    __shared__ int sPbase[PIXTILE];
    __shared__ int sPy[PIXTILE];
    __shared__ int sPx[PIXTILE];

    const int tid = threadIdx.x;
    const int pixBase = blockIdx.x * PIXTILE;
    const int coBase  = blockIdx.y * COTILE;

    if (tid < PIXTILE) {
        int p = pixBase + tid;
        int b = p / HWSZ;
        int rem = p - b * HWSZ;
        int y = rem / WWW;
        int x = rem - y * WWW;
        sPbase[tid] = b * CHWSZ + y * WWW + x;
        sPy[tid] = y;
        sPx[tid] = x;
    }
    __syncthreads();

    const int ty = tid >> 4;   // 0..15 -> 8 output channels each
    const int tx = tid & 15;   // 0..15 -> 8 pixels each (4 f32x2 pairs)

    unsigned long long acc[32];
#pragma unroll
    for (int i = 0; i < 32; i++) acc[i] = 0ull;

    // ---- phase 1: 3x3 conv over src3 ----
    for (int k0 = 0; k0 < K3; k0 += KCHUNK) {
#pragma unroll
        for (int r = 0; r < (KCHUNK * COTILE) / NT; r++) {     // weights
            int idx = r * NT + tid;
            int kk = idx & (KCHUNK - 1);
            int co = idx >> 4;
            float wv = qw3[(coBase + co) * K3 + k0 + kk];
            sA[kk][co] = make_float2(wv, wv);
        }
#pragma unroll
        for (int r = 0; r < (KCHUNK * PIXTILE) / NT; r++) {    // activations (zero-padded halo)
            int idx = r * NT + tid;
            int i  = idx & (PIXTILE - 1);
            int kk = idx >> 7;
            int k  = k0 + kk;
            int ci = k / 9;
            int r9 = k - ci * 9;
            int dy = r9 / 3 - 1;
            int dx = r9 - (r9 / 3) * 3 - 1;
            int y2 = sPy[i] + dy;
            int x2 = sPx[i] + dx;
            float v = 0.0f;
            if ((unsigned)y2 < (unsigned)HHH && (unsigned)x2 < (unsigned)WWW)
                v = __ldg(&src3[sPbase[i] + ci * HWSZ + dy * WWW + dx]);
            sB[kk][i] = v;
        }
        __syncthreads();
#pragma unroll
        for (int kk = 0; kk < KCHUNK; kk++) {
            const ulonglong2* Ap = reinterpret_cast<const ulonglong2*>(&sA[kk][ty * 8]);
            const ulonglong2* Bp = reinterpret_cast<const ulonglong2*>(&sB[kk][tx * 8]);
            ulonglong2 bv0 = Bp[0];
            ulonglong2 bv1 = Bp[1];
#pragma unroll
            for (int c2 = 0; c2 < 4; c2++) {
                ulonglong2 av = Ap[c2];
                ffma2(acc[c2 * 8 + 0], av.x, bv0.x);
                ffma2(acc[c2 * 8 + 1], av.x, bv0.y);
                ffma2(acc[c2 * 8 + 2], av.x, bv1.x);
                ffma2(acc[c2 * 8 + 3], av.x, bv1.y);
                ffma2(acc[c2 * 8 + 4], av.y, bv0.x);
                ffma2(acc[c2 * 8 + 5], av.y, bv0.y);
                ffma2(acc[c2 * 8 + 6], av.y, bv1.x);
                ffma2(acc[c2 * 8 + 7], av.y, bv1.y);
            }
        }
        __syncthreads();
    }

    // ---- phase 2: optional 1x1 shortcut conv over src1 ----
    if (src1 != nullptr) {
        for (int k0 = 0; k0 < K1; k0 += KCHUNK) {
#pragma unroll
            for (int r = 0; r < (KCHUNK * COTILE) / NT; r++) {
                int idx = r * NT + tid;
                int kk = idx & (KCHUNK - 1);
                int co = idx >> 4;
                float wv = qw1x1[(coBase + co) * K1 + k0 + kk];
                sA[kk][co] = make_float2(wv, wv);
            }
#pragma unroll
            for (int r = 0; r < (KCHUNK * PIXTILE) / NT; r++) {
                int idx = r * NT + tid;
                int i  = idx & (PIXTILE - 1);
                int kk = idx >> 7;
                sB[kk][i] = __ldg(&src1[sPbase[i] + (k0 + kk) * HWSZ]);
            }
            __syncthreads();
#pragma unroll
            for (int kk = 0; kk < KCHUNK; kk++) {
                const ulonglong2* Ap = reinterpret_cast<const ulonglong2*>(&sA[kk][ty * 8]);
                const ulonglong2* Bp = reinterpret_cast<const ulonglong2*>(&sB[kk][tx * 8]);
                ulonglong2 bv0 = Bp[0];
                ulonglong2 bv1 = Bp[1];
#pragma unroll
                for (int c2 = 0; c2 < 4; c2++) {
                    ulonglong2 av = Ap[c2];
                    ffma2(acc[c2 * 8 + 0], av.x, bv0.x);
                    ffma2(acc[c2 * 8 + 1], av.x, bv0.y);
                    ffma2(acc[c2 * 8 + 2], av.x, bv1.x);
                    ffma2(acc[c2 * 8 + 3], av.x, bv1.y);
                    ffma2(acc[c2 * 8 + 4], av.y, bv0.x);
                    ffma2(acc[c2 * 8 + 5], av.y, bv0.y);
                    ffma2(acc[c2 * 8 + 6], av.y, bv1.x);
                    ffma2(acc[c2 * 8 + 7], av.y, bv1.y);
                }
            }
            __syncthreads();
        }
    }

    // ---- epilogue: BN + uint4 fake-quant, float2 stores ----
#pragma unroll
    for (int cl = 0; cl < 8; cl++) {
        int c = coBase + ty * 8 + cl;
        float gm = gamma[c], bt = beta[c], mn = mean[c], vr = var[c], st = step[c];
        float rs = 1.0f / sqrtf(vr + EPSF);
#pragma unroll
        for (int j = 0; j < 4; j++) {
            unsigned long long a = acc[(cl >> 1) * 8 + (cl & 1) * 4 + j];
            float lo = __uint_as_float((unsigned)(a & 0xffffffffu));
            float hi = __uint_as_float((unsigned)(a >> 32));
            float ylo = gm * (lo - mn) * rs + bt;
            float yhi = gm * (hi - mn) * rs + bt;
            float qlo = fminf(fmaxf(rintf(ylo / st), 0.0f), 15.0f) * st;
            float qhi = fminf(fmaxf(rintf(yhi / st), 0.0f), 15.0f) * st;
            int i0 = tx * 8 + j * 2;  // even pixel: never crosses an image boundary
            float2* dst = reinterpret_cast<float2*>(&out[sPbase[i0] + c * HWSZ]);
            *dst = make_float2(qlo, qhi);
        }
    }
}

// ---------------- launch ----------------
extern "C" void kernel_launch(void* const* d_in, const int* in_sizes, int n_in,
                              void* d_out, int out_size) {
    const float* x  = (const float*)d_in[0];
    const float* w1 = (const float*)d_in[1];
    const float* w2 = (const float*)d_in[2];
    const float* ws = (const float*)d_in[3];
    const float* g1 = (const float*)d_in[4];
    const float* b1 = (const float*)d_in[5];
    const float* m1 = (const float*)d_in[6];
    const float* v1 = (const float*)d_in[7];
    const float* s1 = (const float*)d_in[8];
    const float* g2 = (const float*)d_in[9];
    const float* b2 = (const float*)d_in[10];
    const float* m2 = (const float*)d_in[11];
    const float* v2 = (const float*)d_in[12];
    const float* s2 = (const float*)d_in[13];
    float* out = (float*)d_out;

    void* p;
    cudaGetSymbolAddress(&p, g_r);   float* rbuf = (float*)p;
    cudaGetSymbolAddress(&p, g_qw1); float* qw1  = (float*)p;
    cudaGetSymbolAddress(&p, g_qw2); float* qw2  = (float*)p;
    cudaGetSymbolAddress(&p, g_qws); float* qws  = (float*)p;

    zero_max_kernel<<<1, 32>>>();
    absmax_kernel<<<148, NT>>>(w1, CCH * K3, 0);
    absmax_kernel<<<148, NT>>>(w2, CCH * K3, 1);
    absmax_kernel<<<64,  NT>>>(ws, CCH * K1, 2);
    quantw_kernel<<<256, NT>>>(w1, qw1, CCH * K3, 0);
    quantw_kernel<<<256, NT>>>(w2, qw2, CCH * K3, 1);
    quantw_kernel<<<64,  NT>>>(ws, qws, CCH * K1, 2);

    dim3 grid(NPIX / PIXTILE, CCH / COTILE);   // (784, 2)
    // conv1: 3x3 on x -> BN1 + uint4 quant -> rbuf
    conv_kernel<<<grid, NT>>>(x, qw1, nullptr, nullptr, g1, b1, m1, v1, s1, rbuf);
    // conv2: 3x3 on rbuf + fused 1x1 shortcut on x -> BN2 + uint4 quant -> out
    conv_kernel<<<grid, NT>>>(rbuf, qw2, x, qws, g2, b2, m2, v2, s2, out);
}

// round 6
// speedup vs baseline: 3.4051x; 3.4034x over previous
#include <cuda_runtime.h>
#include <cuda_bf16.h>
#include <cstdint>

#define BATCH 32
#define CCH 256
#define HWSZ 3136
#define CHWSZ (CCH*HWSZ)
#define NPIX (BATCH*HWSZ)        // 100352
#define PW 58
#define PADHW (PW*PW)            // 3364
#define PIMG (CCH*PADHW)
#define NPAD ((size_t)BATCH*(size_t)PIMG)
#define EPSF 1e-5f

#define MT 128
#define KC 32
#define NTHR 512
#define NGRID (NPIX/MT)          // 784
#define PA 80                    // A smem pitch (bytes) — conflict-free ldmatrix
#define PB 80                    // B smem pitch

// dynamic smem layout
#define OB 0                     // B: 2 x 20480
#define OA 40960                 // A: 2 x 10240
#define OBASE 61440              // int[128] padded-plane base
#define OOB   61952              // int[128] NCHW base
#define OBN   62464              // float[5][256]
#define DSM   67584

// ---------------- device globals ----------------
__device__ __nv_bfloat16 g_x0[NPAD];
__device__ __nv_bfloat16 g_x1[NPAD];
__device__ __nv_bfloat16 g_x2[NPAD];
__device__ __nv_bfloat16 g_rbf[NPAD];
__device__ float         g_sc[(size_t)NPIX*CCH];
__device__ __nv_bfloat16 g_wb1[256*2304];
__device__ __nv_bfloat16 g_wb2[256*2304];
__device__ __nv_bfloat16 g_wbs[256*256];
__device__ unsigned      g_maxbits[4];

// ---------------- helpers ----------------
__device__ __forceinline__ uint32_t smem_u32(const void* p) {
    uint32_t a;
    asm("{ .reg .u64 t; cvta.to.shared.u64 t, %1; cvt.u32.u64 %0, t; }" : "=r"(a) : "l"(p));
    return a;
}
__device__ __forceinline__ void ldsm4(uint32_t* r, uint32_t a) {
    asm volatile("ldmatrix.sync.aligned.m8n8.x4.shared.b16 {%0,%1,%2,%3}, [%4];"
                 : "=r"(r[0]), "=r"(r[1]), "=r"(r[2]), "=r"(r[3]) : "r"(a));
}
__device__ __forceinline__ void mma16816(float* c, const uint32_t* a, const uint32_t* b) {
    asm volatile("mma.sync.aligned.m16n8k16.row.col.f32.bf16.bf16.f32 "
                 "{%0,%1,%2,%3}, {%4,%5,%6,%7}, {%8,%9}, {%0,%1,%2,%3};"
                 : "+f"(c[0]), "+f"(c[1]), "+f"(c[2]), "+f"(c[3])
                 : "r"(a[0]), "r"(a[1]), "r"(a[2]), "r"(a[3]), "r"(b[0]), "r"(b[1]));
}
__device__ __forceinline__ void cpa16(uint32_t d, const void* s) {
    asm volatile("cp.async.ca.shared.global [%0], [%1], 16;" :: "r"(d), "l"(s));
}
__device__ __forceinline__ void cpcommit() { asm volatile("cp.async.commit_group;"); }
__device__ __forceinline__ void cpwait0()  { asm volatile("cp.async.wait_group 0;"); }

// ---------------- prep kernels ----------------
__global__ void zero_max_kernel() { if (threadIdx.x < 4) g_maxbits[threadIdx.x] = 0u; }

__global__ void absmax_kernel(const float* __restrict__ w, int n, int slot) {
    __shared__ unsigned sm[256];
    unsigned m = 0u;
    for (int i = blockIdx.x * blockDim.x + threadIdx.x; i < n; i += gridDim.x * blockDim.x)
        m = max(m, __float_as_uint(fabsf(w[i])));
    sm[threadIdx.x] = m;
    __syncthreads();
    for (int s = 128; s > 0; s >>= 1) {
        if (threadIdx.x < s) sm[threadIdx.x] = max(sm[threadIdx.x], sm[threadIdx.x + s]);
        __syncthreads();
    }
    if (threadIdx.x == 0) atomicMax(&g_maxbits[slot], sm[0]);
}

// integer levels as bf16; 3x3 K-order: k = tap*256 + ci
__global__ void prepw3_kernel(const float* __restrict__ w, __nv_bfloat16* __restrict__ dst,
                              int slot) {
    int idx = blockIdx.x * blockDim.x + threadIdx.x;   // 256*2304
    int n = idx / 2304, k = idx - n * 2304;
    int tap = k >> 8, ci = k & 255;
    float s = __uint_as_float(g_maxbits[slot]) / 7.0f;
    float q = rintf(fminf(fmaxf(w[n * 2304 + ci * 9 + tap] / s, -7.0f), 7.0f));
    dst[n * 2304 + k] = __float2bfloat16_rn(q);
}
__global__ void prepw1_kernel(const float* __restrict__ w, __nv_bfloat16* __restrict__ dst,
                              int slot) {
    int idx = blockIdx.x * blockDim.x + threadIdx.x;   // 256*256
    float s = __uint_as_float(g_maxbits[slot]) / 7.0f;
    float q = rintf(fminf(fmaxf(w[idx] / s, -7.0f), 7.0f));
    dst[idx] = __float2bfloat16_rn(q);
}

// split x into 3 bf16 padded planes (zero border)
__global__ void splitx_kernel(const float* __restrict__ x) {
    size_t i = (size_t)blockIdx.x * blockDim.x + threadIdx.x;
    if (i >= NPAD) return;
    size_t b = i / PIMG;
    int r = (int)(i - b * PIMG);
    int ci = r / PADHW, rr = r - ci * PADHW;
    int py = rr / PW, px = rr - py * PW;
    float v = 0.0f;
    if (py >= 1 && py <= 56 && px >= 1 && px <= 56)
        v = x[b * CHWSZ + (size_t)ci * HWSZ + (py - 1) * 56 + (px - 1)];
    __nv_bfloat16 h0 = __float2bfloat16_rn(v);
    float r1 = v - __bfloat162float(h0);
    __nv_bfloat16 h1 = __float2bfloat16_rn(r1);
    float r2 = r1 - __bfloat162float(h1);
    g_x0[i] = h0; g_x1[i] = h1; g_x2[i] = __float2bfloat16_rn(r2);
}

// ---------------- HMMA implicit-GEMM conv ----------------
// mode 0: shortcut -> g_sc fp32 [ch][pix]
// mode 1: conv1 -> BN1+quant -> bf16 padded plane
// mode 2: conv2 + sc -> BN2+quant -> out fp32 NCHW
__global__ __launch_bounds__(NTHR, 1)
void gemm_kernel(const __nv_bfloat16* __restrict__ p0,
                 const __nv_bfloat16* __restrict__ p1,
                 const __nv_bfloat16* __restrict__ p2,
                 const __nv_bfloat16* __restrict__ wB,
                 int Ktot, int cps, int nsplit, int is3x3, int slot, int mode,
                 const float* __restrict__ gmm, const float* __restrict__ bt,
                 const float* __restrict__ mn,  const float* __restrict__ vr,
                 const float* __restrict__ st,
                 const float* __restrict__ scin,
                 float* __restrict__ outf, __nv_bfloat16* __restrict__ outb) {
    extern __shared__ char dyn[];
    char* base = dyn;
    const uint32_t sb = smem_u32(base);
    const int tid = threadIdx.x, wid = tid >> 5, lid = tid & 31;
    int* sBase = (int*)(base + OBASE);
    int* sOb   = (int*)(base + OOB);
    float* sBN = (float*)(base + OBN);

    if (tid < MT) {
        int p = blockIdx.x * MT + tid;
        int b = p / HWSZ, rem = p - b * HWSZ;
        int y = rem / 56, x = rem - y * 56;
        sBase[tid] = b * PIMG + (y + 1) * PW + (x + 1);
        sOb[tid]   = b * CHWSZ + rem;
    }
    if (tid < 256) {
        sBN[tid]        = gmm[tid];
        sBN[256 + tid]  = bt[tid];
        sBN[512 + tid]  = mn[tid];
        sBN[768 + tid]  = 1.0f / sqrtf(vr[tid] + EPSF);
        sBN[1024 + tid] = st[tid];
    }
    __syncthreads();

    const int am = tid & 127;          // A-gather row
    const int ag = tid >> 7;           // A-gather k-subgroup (0..3) -> kk0 = ag*8
    const int aofs = sBase[am];
    const int m0w = (wid & 3) * 32;    // warp M origin
    const int n0w = (wid >> 2) * 64;   // warp N origin
    const int NCH = nsplit * cps;

    float acc[2][8][4];
#pragma unroll
    for (int i = 0; i < 2; i++)
#pragma unroll
        for (int j = 0; j < 8; j++)
#pragma unroll
            for (int k = 0; k < 4; k++) acc[i][j][k] = 0.0f;

    // ---- A-stage helper state ----
    unsigned short hreg[8];

    // prologue: chunk 0 -> buffer 0
    {
        int td, ci0;
        if (is3x3) { td = -PW - 1; ci0 = 0; } else { td = 0; ci0 = 0; }
        const unsigned short* src =
            (const unsigned short*)(p0 + (size_t)(ci0 + ag * 8) * PADHW) + (aofs + td);
#pragma unroll
        for (int j = 0; j < 8; j++) hreg[j] = src[(size_t)j * PADHW];
        uint4 v;
        v.x = (uint32_t)hreg[0] | ((uint32_t)hreg[1] << 16);
        v.y = (uint32_t)hreg[2] | ((uint32_t)hreg[3] << 16);
        v.z = (uint32_t)hreg[4] | ((uint32_t)hreg[5] << 16);
        v.w = (uint32_t)hreg[6] | ((uint32_t)hreg[7] << 16);
        *(uint4*)(base + OA + am * PA + ag * 16) = v;
#pragma unroll
        for (int i = 0; i < 2; i++) {
            int idx = tid * 2 + i;
            int n = idx >> 2, seg = idx & 3;
            cpa16(sb + OB + n * PB + seg * 16, wB + (size_t)n * Ktot + seg * 8);
        }
        cpcommit();
    }

    for (int c = 0; c < NCH; c++) {
        const int cur = c & 1, nxt = cur ^ 1;
        const bool havenext = (c + 1) < NCH;
        // 1. stage A(c+1) in registers (LDG latency hides behind MMA)
        if (havenext) {
            int cn = c + 1, qn = cn % cps, spn = cn / cps;
            int td, ci0;
            if (is3x3) { int tap = qn >> 3; td = (tap / 3 - 1) * PW + (tap % 3 - 1);
                         ci0 = (qn & 7) * 32; }
            else       { td = 0; ci0 = qn * 32; }
            const __nv_bfloat16* pl = (spn == 0) ? p0 : ((spn == 1) ? p1 : p2);
            const unsigned short* src =
                (const unsigned short*)(pl + (size_t)(ci0 + ag * 8) * PADHW) + (aofs + td);
#pragma unroll
            for (int j = 0; j < 8; j++) hreg[j] = src[(size_t)j * PADHW];
        }
        // 2/3. drain B(c), barrier
        cpwait0();
        __syncthreads();
        // 4. issue B(c+1)
        if (havenext) {
            int qn = (c + 1) % cps;
            int k0 = qn * KC;
#pragma unroll
            for (int i = 0; i < 2; i++) {
                int idx = tid * 2 + i;
                int n = idx >> 2, seg = idx & 3;
                cpa16(sb + OB + nxt * 20480 + n * PB + seg * 16,
                      wB + (size_t)n * Ktot + k0 + seg * 8);
            }
        }
        cpcommit();
        // 5. MMA over buffer cur
        {
            const uint32_t ab = sb + OA + cur * 10240;
            const uint32_t bb = sb + OB + cur * 20480;
#pragma unroll
            for (int s = 0; s < 2; s++) {
                uint32_t afr[2][4];
#pragma unroll
                for (int mi = 0; mi < 2; mi++)
                    ldsm4(afr[mi], ab + (m0w + mi * 16 + (lid & 15)) * PA
                                      + s * 32 + (lid >> 4) * 16);
                uint32_t bfr[8][2];
#pragma unroll
                for (int h = 0; h < 4; h++) {
                    uint32_t r[4];
                    ldsm4(r, bb + (n0w + h * 16 + (lid & 7) + ((lid >> 4) << 3)) * PB
                              + s * 32 + ((lid >> 3) & 1) * 16);
                    bfr[h * 2][0] = r[0]; bfr[h * 2][1] = r[1];
                    bfr[h * 2 + 1][0] = r[2]; bfr[h * 2 + 1][1] = r[3];
                }
#pragma unroll
                for (int mi = 0; mi < 2; mi++)
#pragma unroll
                    for (int ng = 0; ng < 8; ng++)
                        mma16816(acc[mi][ng], afr[mi], bfr[ng]);
            }
        }
        // 6. commit staged A(c+1) to smem
        if (havenext) {
            uint4 v;
            v.x = (uint32_t)hreg[0] | ((uint32_t)hreg[1] << 16);
            v.y = (uint32_t)hreg[2] | ((uint32_t)hreg[3] << 16);
            v.z = (uint32_t)hreg[4] | ((uint32_t)hreg[5] << 16);
            v.w = (uint32_t)hreg[6] | ((uint32_t)hreg[7] << 16);
            *(uint4*)(base + OA + nxt * 10240 + am * PA + ag * 16) = v;
        }
    }
    __syncthreads();

    // ---- epilogue ----
    const float s = __uint_as_float(g_maxbits[slot]) / 7.0f;
    const int gpb = blockIdx.x * MT;
#pragma unroll
    for (int mi = 0; mi < 2; mi++) {
        int mA = m0w + mi * 16 + (lid >> 2);
        int mB = mA + 8;
#pragma unroll
        for (int ng = 0; ng < 8; ng++) {
            int ch = n0w + ng * 8 + (lid & 3) * 2;
            float* a4 = acc[mi][ng];
#pragma unroll
            for (int e = 0; e < 4; e++) {
                int cc = ch + (e & 1);
                int m  = (e < 2) ? mA : mB;
                float v = a4[e] * s;
                if (mode == 0) {
                    outf[(size_t)cc * NPIX + gpb + m] = v;
                } else if (mode == 1) {
                    float y = sBN[cc] * (v - sBN[512 + cc]) * sBN[768 + cc] + sBN[256 + cc];
                    float stp = sBN[1024 + cc];
                    float q = fminf(fmaxf(rintf(y / stp), 0.0f), 15.0f) * stp;
                    outb[sBase[m] + (size_t)cc * PADHW] = __float2bfloat16_rn(q);
                } else {
                    float vv = v + scin[(size_t)cc * NPIX + gpb + m];
                    float y = sBN[cc] * (vv - sBN[512 + cc]) * sBN[768 + cc] + sBN[256 + cc];
                    float stp = sBN[1024 + cc];
                    float q = fminf(fmaxf(rintf(y / stp), 0.0f), 15.0f) * stp;
                    outf[sOb[m] + (size_t)cc * HWSZ] = q;
                }
            }
        }
    }
}

// ---------------- launch ----------------
extern "C" void kernel_launch(void* const* d_in, const int* in_sizes, int n_in,
                              void* d_out, int out_size) {
    const float* x  = (const float*)d_in[0];
    const float* w1 = (const float*)d_in[1];
    const float* w2 = (const float*)d_in[2];
    const float* ws = (const float*)d_in[3];
    const float* g1 = (const float*)d_in[4];
    const float* b1 = (const float*)d_in[5];
    const float* m1 = (const float*)d_in[6];
    const float* v1 = (const float*)d_in[7];
    const float* s1 = (const float*)d_in[8];
    const float* g2 = (const float*)d_in[9];
    const float* b2 = (const float*)d_in[10];
    const float* m2 = (const float*)d_in[11];
    const float* v2 = (const float*)d_in[12];
    const float* s2 = (const float*)d_in[13];
    float* out = (float*)d_out;

    void* p;
    cudaGetSymbolAddress(&p, g_x0);  __nv_bfloat16* x0 = (__nv_bfloat16*)p;
    cudaGetSymbolAddress(&p, g_x1);  __nv_bfloat16* x1 = (__nv_bfloat16*)p;
    cudaGetSymbolAddress(&p, g_x2);  __nv_bfloat16* x2 = (__nv_bfloat16*)p;
    cudaGetSymbolAddress(&p, g_rbf); __nv_bfloat16* rbf = (__nv_bfloat16*)p;
    cudaGetSymbolAddress(&p, g_sc);  float* sc = (float*)p;
    cudaGetSymbolAddress(&p, g_wb1); __nv_bfloat16* wb1 = (__nv_bfloat16*)p;
    cudaGetSymbolAddress(&p, g_wb2); __nv_bfloat16* wb2 = (__nv_bfloat16*)p;
    cudaGetSymbolAddress(&p, g_wbs); __nv_bfloat16* wbs = (__nv_bfloat16*)p;

    cudaFuncSetAttribute(gemm_kernel, cudaFuncAttributeMaxDynamicSharedMemorySize, DSM);

    zero_max_kernel<<<1, 32>>>();
    absmax_kernel<<<148, 256>>>(w1, 256 * 2304, 0);
    absmax_kernel<<<148, 256>>>(w2, 256 * 2304, 1);
    absmax_kernel<<<64,  256>>>(ws, 256 * 256, 2);
    prepw3_kernel<<<2304, 256>>>(w1, wb1, 0);
    prepw3_kernel<<<2304, 256>>>(w2, wb2, 1);
    prepw1_kernel<<<256,  256>>>(ws, wbs, 2);
    splitx_kernel<<<(int)((NPAD + 255) / 256), 256>>>(x);

    // shortcut: 1x1, 3 splits -> g_sc (fp32 planar)
    gemm_kernel<<<NGRID, NTHR, DSM>>>(x0, x1, x2, wbs, 256, 8, 3, 0, 2, 0,
                                      g1, b1, m1, v1, s1, sc, sc, rbf);
    // conv1: 3x3, 3 splits -> BN1+quant -> rbf (padded bf16)
    gemm_kernel<<<NGRID, NTHR, DSM>>>(x0, x1, x2, wb1, 2304, 72, 3, 1, 0, 1,
                                      g1, b1, m1, v1, s1, sc, sc, rbf);
    // conv2: 3x3 on rbf + shortcut add -> BN2+quant -> out (fp32 NCHW)
    gemm_kernel<<<NGRID, NTHR, DSM>>>(rbf, rbf, rbf, wb2, 2304, 72, 1, 1, 1, 2,
                                      g2, b2, m2, v2, s2, sc, out, rbf);
}

// round 8
// speedup vs baseline: 5.1803x; 1.5213x over previous
#include <cuda_runtime.h>
#include <cuda_fp16.h>
#include <cstdint>

#define BATCH 32
#define CCH 256
#define HWSZ 3136
#define CHWSZ (CCH*HWSZ)
#define NPIX (BATCH*HWSZ)        // 100352
#define PW 58
#define PADHW (PW*PW)            // 3364
#define PIMG (CCH*PADHW)
#define NPAD ((size_t)BATCH*(size_t)PIMG)
#define EPSF 1e-5f

#define MT 128
#define KC 64
#define NTHR 512
#define NGRID (NPIX/MT)          // 784
#define PA 144                   // A smem pitch bytes (128 data + 16 pad)
#define PB 144

// dynamic smem layout
#define OB 0                     // B: 2 x 36864
#define OA 73728                 // A: 2 x 18432
#define OBASE 110592             // int[128]
#define OOB   111104             // int[128]
#define OBN   111616             // float[5][256]
#define DSM   116736

// ---------------- device globals ----------------
__device__ __half g_x0[NPAD];
__device__ __half g_x1[NPAD];
__device__ __half g_rbf[NPAD];
__device__ float  g_sc[(size_t)NPIX*CCH];
__device__ __half g_wb1[256*2304];
__device__ __half g_wb2[256*2304];
__device__ __half g_wbs[256*256];
__device__ unsigned g_maxbits[4];

// ---------------- helpers ----------------
__device__ __forceinline__ uint32_t smem_u32(const void* p) {
    uint32_t a;
    asm("{ .reg .u64 t; cvta.to.shared.u64 t, %1; cvt.u32.u64 %0, t; }" : "=r"(a) : "l"(p));
    return a;
}
__device__ __forceinline__ void ldsm4(uint32_t* r, uint32_t a) {
    asm volatile("ldmatrix.sync.aligned.m8n8.x4.shared.b16 {%0,%1,%2,%3}, [%4];"
                 : "=r"(r[0]), "=r"(r[1]), "=r"(r[2]), "=r"(r[3]) : "r"(a));
}
__device__ __forceinline__ void mma16816(float* c, const uint32_t* a, const uint32_t* b) {
    asm volatile("mma.sync.aligned.m16n8k16.row.col.f32.f16.f16.f32 "
                 "{%0,%1,%2,%3}, {%4,%5,%6,%7}, {%8,%9}, {%0,%1,%2,%3};"
                 : "+f"(c[0]), "+f"(c[1]), "+f"(c[2]), "+f"(c[3])
                 : "r"(a[0]), "r"(a[1]), "r"(a[2]), "r"(a[3]), "r"(b[0]), "r"(b[1]));
}
__device__ __forceinline__ void cpa16(uint32_t d, const void* s) {
    asm volatile("cp.async.ca.shared.global [%0], [%1], 16;" :: "r"(d), "l"(s));
}
__device__ __forceinline__ void cpcommit() { asm volatile("cp.async.commit_group;"); }
__device__ __forceinline__ void cpwait0()  { asm volatile("cp.async.wait_group 0;"); }

// ---------------- prep kernels ----------------
__global__ void zero_max_kernel() { if (threadIdx.x < 4) g_maxbits[threadIdx.x] = 0u; }

__global__ void absmax_kernel(const float* __restrict__ w, int n, int slot) {
    __shared__ unsigned sm[256];
    unsigned m = 0u;
    for (int i = blockIdx.x * blockDim.x + threadIdx.x; i < n; i += gridDim.x * blockDim.x)
        m = max(m, __float_as_uint(fabsf(w[i])));
    sm[threadIdx.x] = m;
    __syncthreads();
    for (int s = 128; s > 0; s >>= 1) {
        if (threadIdx.x < s) sm[threadIdx.x] = max(sm[threadIdx.x], sm[threadIdx.x + s]);
        __syncthreads();
    }
    if (threadIdx.x == 0) atomicMax(&g_maxbits[slot], sm[0]);
}

// integer levels as fp16 (exact); 3x3 K-order: k = tap*256 + ci
__global__ void prepw3_kernel(const float* __restrict__ w, __half* __restrict__ dst,
                              int slot) {
    int idx = blockIdx.x * blockDim.x + threadIdx.x;   // 256*2304
    int n = idx / 2304, k = idx - n * 2304;
    int tap = k >> 8, ci = k & 255;
    float s = __uint_as_float(g_maxbits[slot]) / 7.0f;
    float q = rintf(fminf(fmaxf(w[n * 2304 + ci * 9 + tap] / s, -7.0f), 7.0f));
    dst[n * 2304 + k] = __float2half_rn(q);
}
__global__ void prepw1_kernel(const float* __restrict__ w, __half* __restrict__ dst,
                              int slot) {
    int idx = blockIdx.x * blockDim.x + threadIdx.x;   // 256*256
    float s = __uint_as_float(g_maxbits[slot]) / 7.0f;
    float q = rintf(fminf(fmaxf(w[idx] / s, -7.0f), 7.0f));
    dst[idx] = __float2half_rn(q);
}

// split x into 2 fp16 padded planes (zero border): x = h0 + h1 + O(2^-22)
__global__ void splitx_kernel(const float* __restrict__ x) {
    size_t i = (size_t)blockIdx.x * blockDim.x + threadIdx.x;
    if (i >= NPAD) return;
    size_t b = i / PIMG;
    int r = (int)(i - b * PIMG);
    int ci = r / PADHW, rr = r - ci * PADHW;
    int py = rr / PW, px = rr - py * PW;
    float v = 0.0f;
    if (py >= 1 && py <= 56 && px >= 1 && px <= 56)
        v = x[b * CHWSZ + (size_t)ci * HWSZ + (py - 1) * 56 + (px - 1)];
    __half h0 = __float2half_rn(v);
    float r1 = v - __half2float(h0);
    g_x0[i] = h0; g_x1[i] = __float2half_rn(r1);
}

// ---------------- HMMA implicit-GEMM conv ----------------
// mode 0: shortcut -> g_sc fp32 [ch][pix]
// mode 1: conv1 -> BN1+quant -> fp16 padded plane
// mode 2: conv2 + sc -> BN2+quant -> out fp32 NCHW
__global__ __launch_bounds__(NTHR, 1)
void gemm_kernel(const __half* __restrict__ p0,
                 const __half* __restrict__ p1,
                 const __half* __restrict__ wB,
                 int Ktot, int cps, int nsplit, int is3x3, int slot, int mode,
                 const float* __restrict__ gmm, const float* __restrict__ bt,
                 const float* __restrict__ mn,  const float* __restrict__ vr,
                 const float* __restrict__ st,
                 const float* __restrict__ scin,
                 float* __restrict__ outf, __half* __restrict__ outb) {
    extern __shared__ char dyn[];
    char* base = dyn;
    const uint32_t sb = smem_u32(base);
    const int tid = threadIdx.x, wid = tid >> 5, lid = tid & 31;
    int* sBase = (int*)(base + OBASE);
    int* sOb   = (int*)(base + OOB);
    float* sBN = (float*)(base + OBN);

    if (tid < MT) {
        int p = blockIdx.x * MT + tid;
        int b = p / HWSZ, rem = p - b * HWSZ;
        int y = rem / 56, x = rem - y * 56;
        sBase[tid] = b * PIMG + (y + 1) * PW + (x + 1);
        sOb[tid]   = b * CHWSZ + rem;
    }
    if (tid < 256) {
        sBN[tid]        = gmm[tid];
        sBN[256 + tid]  = bt[tid];
        sBN[512 + tid]  = mn[tid];
        sBN[768 + tid]  = 1.0f / sqrtf(vr[tid] + EPSF);
        sBN[1024 + tid] = st[tid];
    }
    __syncthreads();

    const int am = tid & 127;          // A row handled by this thread
    const int ag = tid >> 7;           // k-octet group 0..3
    const int aofs = sBase[am];
    const int m0w = (wid & 3) * 32;    // warp M origin
    const int n0w = (wid >> 2) * 64;   // warp N origin
    const int NCH = nsplit * cps;

    float acc[2][8][4];
#pragma unroll
    for (int i = 0; i < 2; i++)
#pragma unroll
        for (int j = 0; j < 8; j++)
#pragma unroll
            for (int k = 0; k < 4; k++) acc[i][j][k] = 0.0f;

    unsigned short hreg[16];

    // prologue: chunk 0 -> buffer 0
    {
        int td = is3x3 ? (-PW - 1) : 0;
#pragma unroll
        for (int g = 0; g < 2; g++) {
            const unsigned short* src =
                (const unsigned short*)(p0 + (size_t)(ag * 8 + g * 32) * PADHW) + (aofs + td);
#pragma unroll
            for (int j = 0; j < 8; j++) hreg[g * 8 + j] = src[(size_t)j * PADHW];
        }
#pragma unroll
        for (int g = 0; g < 2; g++) {
            uint4 v;
            v.x = (uint32_t)hreg[g*8+0] | ((uint32_t)hreg[g*8+1] << 16);
            v.y = (uint32_t)hreg[g*8+2] | ((uint32_t)hreg[g*8+3] << 16);
            v.z = (uint32_t)hreg[g*8+4] | ((uint32_t)hreg[g*8+5] << 16);
            v.w = (uint32_t)hreg[g*8+6] | ((uint32_t)hreg[g*8+7] << 16);
            *(uint4*)(base + OA + am * PA + g * 64 + ag * 16) = v;
        }
#pragma unroll
        for (int i = 0; i < 4; i++) {
            int idx = tid * 4 + i;
            int n = idx >> 3, seg = idx & 7;
            cpa16(sb + OB + n * PB + seg * 16, wB + (size_t)n * Ktot + seg * 8);
        }
        cpcommit();
    }

    for (int c = 0; c < NCH; c++) {
        const int cur = c & 1, nxt = cur ^ 1;
        const bool havenext = (c + 1) < NCH;
        // 1. stage A(c+1) in registers
        if (havenext) {
            int cn = c + 1, qn = cn % cps, spn = cn / cps;
            int td, ci0;
            if (is3x3) { int tap = qn >> 2; td = (tap / 3 - 1) * PW + (tap % 3 - 1);
                         ci0 = (qn & 3) * 64; }
            else       { td = 0; ci0 = qn * 64; }
            const __half* pl = (spn == 0) ? p0 : p1;
#pragma unroll
            for (int g = 0; g < 2; g++) {
                const unsigned short* src =
                    (const unsigned short*)(pl + (size_t)(ci0 + ag * 8 + g * 32) * PADHW)
                    + (aofs + td);
#pragma unroll
                for (int j = 0; j < 8; j++) hreg[g * 8 + j] = src[(size_t)j * PADHW];
            }
        }
        // 2/3. drain B(c), barrier
        cpwait0();
        __syncthreads();
        // 4. issue B(c+1)
        if (havenext) {
            int k0 = ((c + 1) % cps) * KC;
#pragma unroll
            for (int i = 0; i < 4; i++) {
                int idx = tid * 4 + i;
                int n = idx >> 3, seg = idx & 7;
                cpa16(sb + OB + nxt * 36864 + n * PB + seg * 16,
                      wB + (size_t)n * Ktot + k0 + seg * 8);
            }
        }
        cpcommit();
        // 5. MMA over buffer cur (4 k16 steps)
        {
            const uint32_t ab = sb + OA + cur * 18432;
            const uint32_t bb = sb + OB + cur * 36864;
#pragma unroll
            for (int s = 0; s < 4; s++) {
                uint32_t afr[2][4];
#pragma unroll
                for (int mi = 0; mi < 2; mi++)
                    ldsm4(afr[mi], ab + (m0w + mi * 16 + (lid & 15)) * PA
                                      + s * 32 + (lid >> 4) * 16);
                uint32_t bfr[8][2];
#pragma unroll
                for (int h = 0; h < 4; h++) {
                    uint32_t r[4];
                    ldsm4(r, bb + (n0w + h * 16 + (lid & 7) + ((lid >> 4) << 3)) * PB
                              + s * 32 + ((lid >> 3) & 1) * 16);
                    bfr[h * 2][0] = r[0]; bfr[h * 2][1] = r[1];
                    bfr[h * 2 + 1][0] = r[2]; bfr[h * 2 + 1][1] = r[3];
                }
#pragma unroll
                for (int mi = 0; mi < 2; mi++)
#pragma unroll
                    for (int ng = 0; ng < 8; ng++)
                        mma16816(acc[mi][ng], afr[mi], bfr[ng]);
            }
        }
        // 6. commit staged A(c+1)
        if (havenext) {
#pragma unroll
            for (int g = 0; g < 2; g++) {
                uint4 v;
                v.x = (uint32_t)hreg[g*8+0] | ((uint32_t)hreg[g*8+1] << 16);
                v.y = (uint32_t)hreg[g*8+2] | ((uint32_t)hreg[g*8+3] << 16);
                v.z = (uint32_t)hreg[g*8+4] | ((uint32_t)hreg[g*8+5] << 16);
                v.w = (uint32_t)hreg[g*8+6] | ((uint32_t)hreg[g*8+7] << 16);
                *(uint4*)(base + OA + nxt * 18432 + am * PA + g * 64 + ag * 16) = v;
            }
        }
    }
    __syncthreads();

    // ---- epilogue ----
    const float s = __uint_as_float(g_maxbits[slot]) / 7.0f;
    const int gpb = blockIdx.x * MT;
#pragma unroll
    for (int mi = 0; mi < 2; mi++) {
        int mA = m0w + mi * 16 + (lid >> 2);
        int mB = mA + 8;
#pragma unroll
        for (int ng = 0; ng < 8; ng++) {
            int ch = n0w + ng * 8 + (lid & 3) * 2;
            float* a4 = acc[mi][ng];
#pragma unroll
            for (int e = 0; e < 4; e++) {
                int cc = ch + (e & 1);
                int m  = (e < 2) ? mA : mB;
                float v = a4[e] * s;
                if (mode == 0) {
                    outf[(size_t)cc * NPIX + gpb + m] = v;
                } else if (mode == 1) {
                    float y = sBN[cc] * (v - sBN[512 + cc]) * sBN[768 + cc] + sBN[256 + cc];
                    float stp = sBN[1024 + cc];
                    float q = fminf(fmaxf(rintf(y / stp), 0.0f), 15.0f) * stp;
                    outb[sBase[m] + (size_t)cc * PADHW] = __float2half_rn(q);
                } else {
                    float vv = v + scin[(size_t)cc * NPIX + gpb + m];
                    float y = sBN[cc] * (vv - sBN[512 + cc]) * sBN[768 + cc] + sBN[256 + cc];
                    float stp = sBN[1024 + cc];
                    float q = fminf(fmaxf(rintf(y / stp), 0.0f), 15.0f) * stp;
                    outf[sOb[m] + (size_t)cc * HWSZ] = q;
                }
            }
        }
    }
}

// ---------------- launch ----------------
extern "C" void kernel_launch(void* const* d_in, const int* in_sizes, int n_in,
                              void* d_out, int out_size) {
    const float* x  = (const float*)d_in[0];
    const float* w1 = (const float*)d_in[1];
    const float* w2 = (const float*)d_in[2];
    const float* ws = (const float*)d_in[3];
    const float* g1 = (const float*)d_in[4];
    const float* b1 = (const float*)d_in[5];
    const float* m1 = (const float*)d_in[6];
    const float* v1 = (const float*)d_in[7];
    const float* s1 = (const float*)d_in[8];
    const float* g2 = (const float*)d_in[9];
    const float* b2 = (const float*)d_in[10];
    const float* m2 = (const float*)d_in[11];
    const float* v2 = (const float*)d_in[12];
    const float* s2 = (const float*)d_in[13];
    float* out = (float*)d_out;

    void* p;
    cudaGetSymbolAddress(&p, g_x0);  __half* x0 = (__half*)p;
    cudaGetSymbolAddress(&p, g_x1);  __half* x1 = (__half*)p;
    cudaGetSymbolAddress(&p, g_rbf); __half* rbf = (__half*)p;
    cudaGetSymbolAddress(&p, g_sc);  float* sc = (float*)p;
    cudaGetSymbolAddress(&p, g_wb1); __half* wb1 = (__half*)p;
    cudaGetSymbolAddress(&p, g_wb2); __half* wb2 = (__half*)p;
    cudaGetSymbolAddress(&p, g_wbs); __half* wbs = (__half*)p;

    cudaFuncSetAttribute(gemm_kernel, cudaFuncAttributeMaxDynamicSharedMemorySize, DSM);

    zero_max_kernel<<<1, 32>>>();
    absmax_kernel<<<148, 256>>>(w1, 256 * 2304, 0);
    absmax_kernel<<<148, 256>>>(w2, 256 * 2304, 1);
    absmax_kernel<<<64,  256>>>(ws, 256 * 256, 2);
    prepw3_kernel<<<2304, 256>>>(w1, wb1, 0);
    prepw3_kernel<<<2304, 256>>>(w2, wb2, 1);
    prepw1_kernel<<<256,  256>>>(ws, wbs, 2);
    splitx_kernel<<<(int)((NPAD + 255) / 256), 256>>>(x);

    // shortcut: 1x1, 2 fp16 splits -> g_sc (fp32 planar)
    gemm_kernel<<<NGRID, NTHR, DSM>>>(x0, x1, wbs, 256, 4, 2, 0, 2, 0,
                                      g1, b1, m1, v1, s1, sc, sc, rbf);
    // conv1: 3x3, 2 fp16 splits -> BN1+quant -> rbf (padded fp16)
    gemm_kernel<<<NGRID, NTHR, DSM>>>(x0, x1, wb1, 2304, 36, 2, 1, 0, 1,
                                      g1, b1, m1, v1, s1, sc, sc, rbf);
    // conv2: 3x3 on rbf (exact fp16) + shortcut -> BN2+quant -> out (fp32 NCHW)
    gemm_kernel<<<NGRID, NTHR, DSM>>>(rbf, rbf, wb2, 2304, 36, 1, 1, 1, 2,
                                      g2, b2, m2, v2, s2, sc, out, rbf);
}